// round 4
// baseline (speedup 1.0000x reference)
#include <cuda_runtime.h>
#include <cuda_bf16.h>
#include <cstdint>
#include <math.h>

#define BATCH   65536
#define NUMC    512
#define DIM     256
#define BM      128
#define BN      128
#define NT      (NUMC/BN)      // 4
#define THREADS 256
#define NBLOCKS (BATCH/BM)     // 512
#define ALPHA   0.05f
#define FINF    3.402823466e38f

// smem byte offsets
#define SAS     0              // A tile bf16 128x256 swizzled       (65536)
#define SB0     65536          // B buf 0                            (65536)
#define SB1     131072         // B buf 1                            (65536)
#define SCSQ    196608         // 512 f                              (2048)
#define SXSQ    198656         // 128 f                              (512)
#define SMINB   199168         // 128x2 f                            (1024)
#define SRED    200192         // 4 f + pad                          (64)
#define SMEM_TOTAL 200256

__device__ float g_csq[NUMC];
__device__ __align__(16) uint32_t g_cenB[NUMC * DIM / 2];  // bf16x2, [n][k]
__device__ float g_partials[NBLOCKS];

// ---------------- helpers ----------------
__device__ __forceinline__ uint32_t smem_u32(const void* p) {
    uint32_t a;
    asm("{ .reg .u64 t; cvta.to.shared.u64 t, %1; cvt.u32.u64 %0, t; }"
        : "=r"(a) : "l"(p));
    return a;
}
__device__ __forceinline__ uint32_t bf16pair(float lo, float hi) {
    uint32_t r;
    asm("cvt.rn.satfinite.bf16x2.f32 %0, %1, %2;" : "=r"(r) : "f"(hi), "f"(lo));
    return r;
}
__device__ __forceinline__ void mma16816(float c[4], const uint32_t a[4],
                                         uint32_t b0, uint32_t b1) {
    asm volatile(
        "mma.sync.aligned.m16n8k16.row.col.f32.bf16.bf16.f32 "
        "{%0,%1,%2,%3}, {%4,%5,%6,%7}, {%8,%9}, {%0,%1,%2,%3};"
        : "+f"(c[0]), "+f"(c[1]), "+f"(c[2]), "+f"(c[3])
        : "r"(a[0]), "r"(a[1]), "r"(a[2]), "r"(a[3]), "r"(b0), "r"(b1));
}
#define LDSM4(r, a)                                                            \
    asm volatile("ldmatrix.sync.aligned.m8n8.x4.shared.b16 {%0,%1,%2,%3}, [%4];" \
        : "=r"((r)[0]), "=r"((r)[1]), "=r"((r)[2]), "=r"((r)[3]) : "r"(a))
#define CP_ASYNC16(dst, src) \
    asm volatile("cp.async.cg.shared.global [%0], [%1], 16;" :: "r"(dst), "l"(src))
#define CP_COMMIT()  asm volatile("cp.async.commit_group;" ::: "memory")
#define CP_WAIT0()   asm volatile("cp.async.wait_group 0;" ::: "memory")

// ---------------------------------------------------------------------------
// Kernel 0: center norms (exact fp32) + bf16 copy of centers, [n][k] layout.
// ---------------------------------------------------------------------------
__global__ void prep_kernel(const float* __restrict__ cen) {
    int w    = blockIdx.x * 8 + (threadIdx.x >> 5);
    int lane = threadIdx.x & 31;
    const float2* row = (const float2*)(cen + (size_t)w * DIM);
    float s = 0.f;
    #pragma unroll
    for (int i = 0; i < 4; i++) {
        float2 v = row[lane + 32 * i];
        s += v.x * v.x + v.y * v.y;
        g_cenB[w * (DIM / 2) + lane + 32 * i] = bf16pair(v.x, v.y);
    }
    #pragma unroll
    for (int off = 16; off; off >>= 1)
        s += __shfl_xor_sync(0xffffffffu, s, off);
    if (lane == 0) g_csq[w] = s;
}

// ---------------------------------------------------------------------------
// Kernel 1: bf16 mma.sync GEMM fused with row-min + sqrt + block reduction.
// ldmatrix.x4 fragment loads, register double-buffered across k-steps.
// ---------------------------------------------------------------------------
extern __shared__ char smem[];

__device__ __forceinline__ void cp_tile(uint32_t sb_dst, int t, int tid) {
    const char* src = (const char*)g_cenB + (size_t)t * BN * 512;
    #pragma unroll
    for (int s = 0; s < 16; s++) {
        int idx = tid + s * THREADS;
        int n = idx >> 5, c16 = idx & 31;
        uint32_t dst = sb_dst + n * 512 + (uint32_t)((c16 ^ (n & 7)) << 4);
        CP_ASYNC16(dst, src + n * 512 + c16 * 16);
    }
    CP_COMMIT();
}

__global__ void __launch_bounds__(THREADS, 1)
kmeans_main(const float* __restrict__ emb) {
    const uint32_t sb = smem_u32(smem);
    const int tid   = threadIdx.x;
    const int w     = tid >> 5, lane = tid & 31;
    const int tig   = lane & 3;
    const int warpM = w >> 1, warpN = w & 1;
    const int m0    = warpM * 32;

    // kick off B tile 0 first (overlaps the A prologue)
    cp_tile(sb + SB0, 0, tid);

    // ---- A load: 2 threads per row, convert to bf16, swizzled store, xsq ----
    {
        int row = tid >> 1, half = tid & 1;
        const float4* src = (const float4*)emb
                          + (size_t)(blockIdx.x * BM + row) * (DIM / 4) + half * 32;
        char* dstrow = smem + SAS + row * 512;
        const int key = row & 7;
        float xs = 0.f;
        #pragma unroll
        for (int j = 0; j < 32; j++) {
            float4 v = src[j];
            xs += v.x * v.x + v.y * v.y + v.z * v.z + v.w * v.w;
            int c4 = half * 32 + j;
            uint2 pk;
            pk.x = bf16pair(v.x, v.y);
            pk.y = bf16pair(v.z, v.w);
            *(uint2*)(dstrow + (((c4 >> 1) ^ key) << 4) + ((c4 & 1) << 3)) = pk;
        }
        xs += __shfl_xor_sync(0xffffffffu, xs, 1);
        if (!half) ((float*)(smem + SXSQ))[row] = xs;
    }
    ((float*)(smem + SCSQ))[tid]       = g_csq[tid];
    ((float*)(smem + SCSQ))[tid + 256] = g_csq[tid + 256];

    CP_WAIT0();
    __syncthreads();

    // ---- ldmatrix per-lane base addresses (XOR-foldable swizzle) ----
    // A frag (mi): lane L -> row m0+mi*16+(L&15), chunk parity hi=L>>4
    uint32_t AB[2];
    {
        const uint32_t kk = lane & 7, hi = lane >> 4;
        #pragma unroll
        for (int mi = 0; mi < 2; mi++)
            AB[mi] = sb + SAS + (uint32_t)(m0 + mi * 16 + (lane & 15)) * 512
                   + (((hi ^ kk) & 7) << 4);
    }
    // B frag pair p: lane L -> n = warpN*64 + p*16 + (L>>4)*8 + (L&7),
    //                chunk parity = (L>>3)&1
    uint32_t BB[2][4];
    {
        const uint32_t kk = lane & 7, cp = (lane >> 3) & 1;
        #pragma unroll
        for (int p = 0; p < 4; p++) {
            uint32_t n = warpN * 64 + p * 16 + (lane >> 4) * 8 + (lane & 7);
            uint32_t rel = n * 512 + (((cp ^ kk) & 7) << 4);
            BB[0][p] = sb + SB0 + rel;
            BB[1][p] = sb + SB1 + rel;
        }
    }

    const float* csq_s = (const float*)(smem + SCSQ);
    float rm[2][2] = {{FINF, FINF}, {FINF, FINF}};

    for (int t = 0; t < NT; t++) {
        if (t + 1 < NT)
            cp_tile(sb + (((t + 1) & 1) ? SB1 : SB0), t + 1, tid);
        const int tb = t & 1;

        float c[2][8][4];
        #pragma unroll
        for (int mi = 0; mi < 2; mi++)
            #pragma unroll
            for (int nj = 0; nj < 8; nj++)
                #pragma unroll
                for (int q = 0; q < 4; q++) c[mi][nj][q] = 0.f;

        uint32_t afr[2][2][4], bfr[2][4][4];
        // preload ks = 0
        #pragma unroll
        for (int mi = 0; mi < 2; mi++) LDSM4(afr[0][mi], AB[mi]);
        #pragma unroll
        for (int p = 0; p < 4; p++)    LDSM4(bfr[0][p], BB[tb][p]);

        #pragma unroll
        for (int ks = 0; ks < 16; ks++) {
            const int cur = ks & 1, nxt = cur ^ 1;
            if (ks < 15) {
                const uint32_t ko = (uint32_t)(ks + 1) << 5;
                #pragma unroll
                for (int mi = 0; mi < 2; mi++) LDSM4(afr[nxt][mi], AB[mi] ^ ko);
                #pragma unroll
                for (int p = 0; p < 4; p++)    LDSM4(bfr[nxt][p], BB[tb][p] ^ ko);
            }
            #pragma unroll
            for (int p = 0; p < 4; p++) {
                mma16816(c[0][2*p],   afr[cur][0], bfr[cur][p][0], bfr[cur][p][1]);
                mma16816(c[1][2*p],   afr[cur][1], bfr[cur][p][0], bfr[cur][p][1]);
                mma16816(c[0][2*p+1], afr[cur][0], bfr[cur][p][2], bfr[cur][p][3]);
                mma16816(c[1][2*p+1], afr[cur][1], bfr[cur][p][2], bfr[cur][p][3]);
            }
        }

        // epilogue: cand = ||c||^2 - 2 x.c ; running min
        #pragma unroll
        for (int mi = 0; mi < 2; mi++)
            #pragma unroll
            for (int nj = 0; nj < 8; nj++) {
                int col = t * BN + warpN * 64 + nj * 8 + 2 * tig;
                float q0 = csq_s[col]     - 2.f * c[mi][nj][0];
                float q1 = csq_s[col + 1] - 2.f * c[mi][nj][1];
                float q2 = csq_s[col]     - 2.f * c[mi][nj][2];
                float q3 = csq_s[col + 1] - 2.f * c[mi][nj][3];
                rm[mi][0] = fminf(rm[mi][0], fminf(q0, q1));
                rm[mi][1] = fminf(rm[mi][1], fminf(q2, q3));
            }

        if (t + 1 < NT) { CP_WAIT0(); __syncthreads(); }
    }

    // ---- reduction: min across tig lanes, across warpN, then sqrt & sum ----
    float* minb = (float*)(smem + SMINB);
    const int g = lane >> 2;
    #pragma unroll
    for (int mi = 0; mi < 2; mi++)
        #pragma unroll
        for (int h = 0; h < 2; h++) {
            float v = rm[mi][h];
            v = fminf(v, __shfl_xor_sync(0xffffffffu, v, 1));
            v = fminf(v, __shfl_xor_sync(0xffffffffu, v, 2));
            if (tig == 0)
                minb[(m0 + mi * 16 + g + 8 * h) * 2 + warpN] = v;
        }
    __syncthreads();
    if (tid < 128) {
        float m  = fminf(minb[2 * tid], minb[2 * tid + 1]);
        float xs = ((float*)(smem + SXSQ))[tid];
        float d  = sqrtf(fmaxf(xs + m, 0.f));
        #pragma unroll
        for (int off = 16; off; off >>= 1)
            d += __shfl_xor_sync(0xffffffffu, d, off);
        if (lane == 0) ((float*)(smem + SRED))[w] = d;
    }
    __syncthreads();
    if (tid == 0) {
        float* red = (float*)(smem + SRED);
        g_partials[blockIdx.x] = (red[0] + red[1]) + (red[2] + red[3]);
    }
}

// ---------------------------------------------------------------------------
// Kernel 2: deterministic tree reduce of 512 block partials -> scalar.
// ---------------------------------------------------------------------------
__global__ void finalize_kernel(float* __restrict__ out) {
    __shared__ float s[512];
    int tid = threadIdx.x;
    s[tid] = g_partials[tid];
    __syncthreads();
    #pragma unroll
    for (int off = 256; off; off >>= 1) {
        if (tid < off) s[tid] += s[tid + off];
        __syncthreads();
    }
    if (tid == 0) out[0] = s[0] * (ALPHA / (float)BATCH);
}

// ---------------------------------------------------------------------------
extern "C" void kernel_launch(void* const* d_in, const int* in_sizes, int n_in,
                              void* d_out, int out_size) {
    const float* emb;
    const float* cen;
    if (in_sizes[0] == BATCH * DIM) {
        emb = (const float*)d_in[0];
        cen = (const float*)d_in[1];
    } else {
        emb = (const float*)d_in[1];
        cen = (const float*)d_in[0];
    }
    float* out = (float*)d_out;

    cudaFuncSetAttribute(kmeans_main,
                         cudaFuncAttributeMaxDynamicSharedMemorySize, SMEM_TOTAL);

    prep_kernel<<<NUMC / 8, 256>>>(cen);
    kmeans_main<<<NBLOCKS, THREADS, SMEM_TOTAL>>>(emb);
    finalize_kernel<<<1, 512>>>(out);
}